// round 9
// baseline (speedup 1.0000x reference)
#include <cuda_runtime.h>
#include <cuda_bf16.h>
#include <cstdint>

// Problem constants (SAGEEncoder: N=50000, E=800000, IN=128, HID=128, OUT=64)
#define NMAX 50000
#define EMAX 800000
#define D_IN 128
#define D_HID 128
#define D_OUT 64

#define SCAN_TILE 512
#define SCAN_NBLK ((NMAX + SCAN_TILE - 1) / SCAN_TILE)   // 98

// ---------------- scratch (static device globals; no allocation) -------------
__device__ __align__(16) int   g_deg[NMAX];
__device__ __align__(16) int   g_rowstart[NMAX + 1];
__device__ __align__(16) int   g_cursor[NMAX];
__device__ __align__(16) int   g_csr[EMAX];
__device__ __align__(16) int   g_tilesum[SCAN_NBLK];
__device__ __align__(16) int   g_tileoff[SCAN_NBLK];
__device__ __align__(16) float g_t1[(size_t)NMAX * 256]; // [n][0:128)=feat@Wself1, [128:256)=feat@Wneigh1
__device__ __align__(16) float g_h1[(size_t)NMAX * 128]; // relu'd layer-1 output
__device__ __align__(16) float g_t2[(size_t)NMAX * 128]; // [n][0:64)=h1@Wself2, [64:128)=h1@Wneigh2
__device__ int g_is64;

// ---------------- index dtype detection --------------------------------------
__global__ void detect_kernel(const int* __restrict__ idx32, int E) {
    __shared__ int nz;
    if (threadIdx.x == 0) nz = 0;
    __syncthreads();
    int i = threadIdx.x;
    if (idx32[2 * i + 1] != 0) atomicAdd(&nz, 1);
    __syncthreads();
    if (threadIdx.x == 0) g_is64 = (nz == 0) ? 1 : 0;
}

__device__ __forceinline__ int load_idx(const void* p, int e, int is64) {
    if (is64) return (int)((const long long*)p)[e];
    return ((const int*)p)[e];
}

// ---------------- CSR build --------------------------------------------------
__global__ void zero_deg_kernel(int n) {
    int i = blockIdx.x * blockDim.x + threadIdx.x;
    if (i < n) g_deg[i] = 0;
}

__global__ void hist_kernel(const void* __restrict__ dst, int E) {
    int is64 = g_is64;
    for (int e = blockIdx.x * blockDim.x + threadIdx.x; e < E; e += gridDim.x * blockDim.x)
        atomicAdd(&g_deg[load_idx(dst, e, is64)], 1);
}

__global__ void scanA_kernel(int n) {
    __shared__ int red[SCAN_TILE];
    int t = threadIdx.x;
    int i = blockIdx.x * SCAN_TILE + t;
    red[t] = (i < n) ? g_deg[i] : 0;
    __syncthreads();
    for (int off = SCAN_TILE / 2; off > 0; off >>= 1) {
        if (t < off) red[t] += red[t + off];
        __syncthreads();
    }
    if (t == 0) g_tilesum[blockIdx.x] = red[0];
}

__global__ void scanB_kernel() {
    __shared__ int s[128];
    int t = threadIdx.x;
    s[t] = (t < SCAN_NBLK) ? g_tilesum[t] : 0;
    __syncthreads();
    for (int off = 1; off < 128; off <<= 1) {
        int v = (t >= off) ? s[t - off] : 0;
        __syncthreads();
        s[t] += v;
        __syncthreads();
    }
    if (t < SCAN_NBLK) g_tileoff[t] = (t == 0) ? 0 : s[t - 1];
}

__global__ void scanC_kernel(int n, int E) {
    __shared__ int s[SCAN_TILE];
    int t = threadIdx.x;
    int i = blockIdx.x * SCAN_TILE + t;
    int v = (i < n) ? g_deg[i] : 0;
    s[t] = v;
    __syncthreads();
    for (int off = 1; off < SCAN_TILE; off <<= 1) {
        int u = (t >= off) ? s[t - off] : 0;
        __syncthreads();
        s[t] += u;
        __syncthreads();
    }
    if (i < n) {
        int excl = g_tileoff[blockIdx.x] + s[t] - v;
        g_rowstart[i] = excl;
        g_cursor[i]   = excl;
        if (i == n - 1) g_rowstart[n] = E;
    }
}

__global__ void scatter_kernel(const void* __restrict__ src,
                               const void* __restrict__ dst, int E) {
    int is64 = g_is64;
    for (int e = blockIdx.x * blockDim.x + threadIdx.x; e < E; e += gridDim.x * blockDim.x) {
        int d = load_idx(dst, e, is64);
        int pos = atomicAdd(&g_cursor[d], 1);
        g_csr[pos] = load_idx(src, e, is64);
    }
}

// ---------------- tf32-split tensor-core dual GEMM ---------------------------
// C[M x 2*halfN] = A[M x K] @ [W0 | W1] using mma.m16n8k8 tf32, 3-term split.
#define TBM 128
#define TBN 128
#define TBK 32
#define APAD 8
#define ASTR (TBM + APAD)
#define WSTR (TBN + APAD)

__device__ __forceinline__ uint32_t f2tf(float x) {
    uint32_t r;
    asm("cvt.rna.tf32.f32 %0, %1;" : "=r"(r) : "f"(x));
    return r;
}

__device__ __forceinline__ void mma_tf32(float* c, uint32_t a0, uint32_t a1,
                                         uint32_t a2, uint32_t a3,
                                         uint32_t b0, uint32_t b1) {
    asm volatile(
        "mma.sync.aligned.m16n8k8.row.col.f32.tf32.tf32.f32 "
        "{%0,%1,%2,%3}, {%4,%5,%6,%7}, {%8,%9}, {%0,%1,%2,%3};"
        : "+f"(c[0]), "+f"(c[1]), "+f"(c[2]), "+f"(c[3])
        : "r"(a0), "r"(a1), "r"(a2), "r"(a3), "r"(b0), "r"(b1));
}

__global__ __launch_bounds__(256) void gemm_tf32_kernel(
    const float* __restrict__ Aext,
    const float* __restrict__ W0,
    const float* __restrict__ W1,
    int M, int K, int halfN, int layer)
{
    const float* __restrict__ A = (layer == 1) ? Aext : g_h1;
    float* __restrict__ C       = (layer == 1) ? g_t1 : g_t2;

    const int N  = 2 * halfN;
    const int bn = blockIdx.x * TBN;
    const int bm = blockIdx.y * TBM;

    __shared__ float As[TBK][ASTR];   // transposed A tile: As[k][row]
    __shared__ float Ws[TBK][WSTR];   // Ws[k][col]

    const int tid  = threadIdx.x;
    const int lane = tid & 31;
    const int warp = tid >> 5;
    const int wm = warp >> 1;
    const int wn = warp & 1;

    const int arow  = tid >> 1;
    const int akb   = (tid & 1) * 16;
    const int aValid = (bm + arow < M);
    const int bkr   = tid >> 3;
    const int bcb   = (tid & 7) * 16;
    const int gcol0 = bn + bcb;
    const float* __restrict__ Wp = (gcol0 < halfN) ? W0 : W1;
    const int wc = (gcol0 < halfN) ? gcol0 : gcol0 - halfN;

    float acc[2][8][4];
#pragma unroll
    for (int i = 0; i < 2; i++)
#pragma unroll
        for (int j = 0; j < 8; j++)
#pragma unroll
            for (int q = 0; q < 4; q++) acc[i][j][q] = 0.f;

    for (int k0 = 0; k0 < K; k0 += TBK) {
#pragma unroll
        for (int v = 0; v < 4; v++) {
            float4 av = make_float4(0.f, 0.f, 0.f, 0.f);
            if (aValid)
                av = *reinterpret_cast<const float4*>(
                    &A[(size_t)(bm + arow) * K + k0 + akb + v * 4]);
            As[akb + v * 4 + 0][arow] = av.x;
            As[akb + v * 4 + 1][arow] = av.y;
            As[akb + v * 4 + 2][arow] = av.z;
            As[akb + v * 4 + 3][arow] = av.w;
        }
#pragma unroll
        for (int v = 0; v < 4; v++) {
            float4 bv = *reinterpret_cast<const float4*>(
                &Wp[(size_t)(k0 + bkr) * halfN + wc + v * 4]);
            *reinterpret_cast<float4*>(&Ws[bkr][bcb + v * 4]) = bv;
        }
        __syncthreads();

#pragma unroll
        for (int ks = 0; ks < TBK / 8; ks++) {
            const int kb = ks * 8;
            uint32_t bhi[8][2], blo[8][2];
#pragma unroll
            for (int nj = 0; nj < 8; nj++) {
                int c = wn * 64 + nj * 8 + (lane >> 2);
                float b0 = Ws[kb + (lane & 3)][c];
                float b1 = Ws[kb + 4 + (lane & 3)][c];
                bhi[nj][0] = f2tf(b0);
                blo[nj][0] = f2tf(b0 - __uint_as_float(bhi[nj][0]));
                bhi[nj][1] = f2tf(b1);
                blo[nj][1] = f2tf(b1 - __uint_as_float(bhi[nj][1]));
            }
#pragma unroll
            for (int mi = 0; mi < 2; mi++) {
                int r = wm * 32 + mi * 16 + (lane >> 2);
                float a0 = As[kb + (lane & 3)][r];
                float a1 = As[kb + (lane & 3)][r + 8];
                float a2 = As[kb + 4 + (lane & 3)][r];
                float a3 = As[kb + 4 + (lane & 3)][r + 8];
                uint32_t ah0 = f2tf(a0), ah1 = f2tf(a1), ah2 = f2tf(a2), ah3 = f2tf(a3);
                uint32_t al0 = f2tf(a0 - __uint_as_float(ah0));
                uint32_t al1 = f2tf(a1 - __uint_as_float(ah1));
                uint32_t al2 = f2tf(a2 - __uint_as_float(ah2));
                uint32_t al3 = f2tf(a3 - __uint_as_float(ah3));
#pragma unroll
                for (int nj = 0; nj < 8; nj++) {
                    mma_tf32(acc[mi][nj], ah0, ah1, ah2, ah3, bhi[nj][0], bhi[nj][1]);
                    mma_tf32(acc[mi][nj], ah0, ah1, ah2, ah3, blo[nj][0], blo[nj][1]);
                    mma_tf32(acc[mi][nj], al0, al1, al2, al3, bhi[nj][0], bhi[nj][1]);
                }
            }
        }
        __syncthreads();
    }

#pragma unroll
    for (int mi = 0; mi < 2; mi++) {
        int r0 = bm + wm * 32 + mi * 16 + (lane >> 2);
#pragma unroll
        for (int nj = 0; nj < 8; nj++) {
            int col = bn + wn * 64 + nj * 8 + (lane & 3) * 2;
            if (r0 < M)
                *reinterpret_cast<float2*>(&C[(size_t)r0 * N + col]) =
                    make_float2(acc[mi][nj][0], acc[mi][nj][1]);
            if (r0 + 8 < M)
                *reinterpret_cast<float2*>(&C[(size_t)(r0 + 8) * N + col]) =
                    make_float2(acc[mi][nj][2], acc[mi][nj][3]);
        }
    }
}

// ---------------- aggregation + epilogue (4-way MLP unroll) ------------------
__global__ void agg_epilogue1_kernel(const float* __restrict__ b1, int n) {
    int node = blockIdx.x * blockDim.y + threadIdx.y;
    if (node >= n) return;
    int j = threadIdx.x;   // 0..127
    int beg = g_rowstart[node];
    int end = g_rowstart[node + 1];
    float acc = 0.f;
    int e = beg;
    for (; e + 4 <= end; e += 4) {
        int s0 = g_csr[e], s1 = g_csr[e + 1], s2 = g_csr[e + 2], s3 = g_csr[e + 3];
        float v0 = g_t1[(size_t)s0 * 256 + 128 + j];
        float v1 = g_t1[(size_t)s1 * 256 + 128 + j];
        float v2 = g_t1[(size_t)s2 * 256 + 128 + j];
        float v3 = g_t1[(size_t)s3 * 256 + 128 + j];
        acc += (v0 + v1) + (v2 + v3);
    }
    for (; e < end; e++)
        acc += g_t1[(size_t)g_csr[e] * 256 + 128 + j];
    float inv = 1.f / fmaxf((float)(end - beg), 1.f);
    float v = g_t1[(size_t)node * 256 + j] + acc * inv + b1[j];
    g_h1[(size_t)node * 128 + j] = fmaxf(v, 0.f);
}

__global__ void agg_epilogue2_kernel(const float* __restrict__ b2,
                                     float* __restrict__ out, int n) {
    int node = blockIdx.x * blockDim.y + threadIdx.y;
    if (node >= n) return;
    int j = threadIdx.x;   // 0..63
    int beg = g_rowstart[node];
    int end = g_rowstart[node + 1];
    float acc = 0.f;
    int e = beg;
    for (; e + 4 <= end; e += 4) {
        int s0 = g_csr[e], s1 = g_csr[e + 1], s2 = g_csr[e + 2], s3 = g_csr[e + 3];
        float v0 = g_t2[(size_t)s0 * 128 + 64 + j];
        float v1 = g_t2[(size_t)s1 * 128 + 64 + j];
        float v2 = g_t2[(size_t)s2 * 128 + 64 + j];
        float v3 = g_t2[(size_t)s3 * 128 + 64 + j];
        acc += (v0 + v1) + (v2 + v3);
    }
    for (; e < end; e++)
        acc += g_t2[(size_t)g_csr[e] * 128 + 64 + j];
    float inv = 1.f / fmaxf((float)(end - beg), 1.f);
    out[(size_t)node * 64 + j] = g_t2[(size_t)node * 128 + j] + acc * inv + b2[j];
}

// ---------------- launch (sequential, single stream — fork regressed) --------
extern "C" void kernel_launch(void* const* d_in, const int* in_sizes, int n_in,
                              void* d_out, int out_size) {
    const float* feat     = (const float*)d_in[0];
    const void*  src      = d_in[1];
    const void*  dst      = d_in[2];
    const float* W_self1  = (const float*)d_in[3];
    const float* W_neigh1 = (const float*)d_in[4];
    const float* b1       = (const float*)d_in[5];
    const float* W_self2  = (const float*)d_in[6];
    const float* W_neigh2 = (const float*)d_in[7];
    const float* b2       = (const float*)d_in[8];
    float* out = (float*)d_out;

    const int N = in_sizes[0] / D_IN;   // 50000
    const int E = in_sizes[1];          // 800000

    // ---- index dtype detection + CSR build (shared by both layers)
    detect_kernel<<<1, 256>>>((const int*)dst, E);
    zero_deg_kernel<<<(N + 255) / 256, 256>>>(N);
    hist_kernel<<<2048, 256>>>(dst, E);
    scanA_kernel<<<SCAN_NBLK, SCAN_TILE>>>(N);
    scanB_kernel<<<1, 128>>>();
    scanC_kernel<<<SCAN_NBLK, SCAN_TILE>>>(N, E);
    scatter_kernel<<<2048, 256>>>(src, dst, E);

    // ---- layer 1: feat @ [W_self1 | W_neigh1] -> g_t1 [N x 256]
    {
        dim3 grid(256 / TBN, (N + TBM - 1) / TBM);
        gemm_tf32_kernel<<<grid, 256>>>(feat, W_self1, W_neigh1, N, D_IN, D_HID, 1);
    }
    {
        dim3 block(128, 2);
        agg_epilogue1_kernel<<<(N + 1) / 2, block>>>(b1, N);
    }

    // ---- layer 2: g_h1 @ [W_self2 | W_neigh2] -> g_t2 [N x 128]
    {
        dim3 grid(128 / TBN, (N + TBM - 1) / TBM);
        gemm_tf32_kernel<<<grid, 256>>>(feat, W_self2, W_neigh2, N, D_HID, D_OUT, 2);
    }
    {
        dim3 block(64, 4);
        agg_epilogue2_kernel<<<(N + 3) / 4, block>>>(b2, out, N);
    }
}

// round 10
// speedup vs baseline: 1.7017x; 1.7017x over previous
#include <cuda_runtime.h>
#include <cuda_bf16.h>
#include <cstdint>

// Problem constants (SAGEEncoder: N=50000, E=800000, IN=128, HID=128, OUT=64)
#define NMAX 50000
#define EMAX 800000
#define D_IN 128
#define D_HID 128
#define D_OUT 64

#define SCAN_TILE 512
#define SCAN_NBLK ((NMAX + SCAN_TILE - 1) / SCAN_TILE)   // 98

// ---------------- scratch (static device globals; no allocation) -------------
__device__ __align__(16) int   g_deg[NMAX];
__device__ __align__(16) int   g_rowstart[NMAX + 1];
__device__ __align__(16) int   g_cursor[NMAX];
__device__ __align__(16) int   g_csr[EMAX];
__device__ __align__(16) int   g_tilesum[SCAN_NBLK];
__device__ __align__(16) int   g_tileoff[SCAN_NBLK];
__device__ __align__(16) float g_t1[(size_t)NMAX * 256]; // [n][0:128)=feat@Wself1, [128:256)=feat@Wneigh1
__device__ __align__(16) float g_h1[(size_t)NMAX * 128]; // relu'd layer-1 output
__device__ __align__(16) float g_t2[(size_t)NMAX * 128]; // [n][0:64)=h1@Wself2, [64:128)=h1@Wneigh2
__device__ int g_is64;

// ---------------- index dtype detection --------------------------------------
__global__ void detect_kernel(const int* __restrict__ idx32, int E) {
    __shared__ int nz;
    if (threadIdx.x == 0) nz = 0;
    __syncthreads();
    int i = threadIdx.x;
    if (idx32[2 * i + 1] != 0) atomicAdd(&nz, 1);
    __syncthreads();
    if (threadIdx.x == 0) g_is64 = (nz == 0) ? 1 : 0;
}

__device__ __forceinline__ int load_idx(const void* p, int e, int is64) {
    if (is64) return (int)((const long long*)p)[e];
    return ((const int*)p)[e];
}

// ---------------- CSR build --------------------------------------------------
__global__ void zero_deg_kernel(int n) {
    int i = blockIdx.x * blockDim.x + threadIdx.x;
    if (i < n) g_deg[i] = 0;
}

__global__ void hist_kernel(const void* __restrict__ dst, int E) {
    int is64 = g_is64;
    for (int e = blockIdx.x * blockDim.x + threadIdx.x; e < E; e += gridDim.x * blockDim.x)
        atomicAdd(&g_deg[load_idx(dst, e, is64)], 1);
}

__global__ void scanA_kernel(int n) {
    __shared__ int red[SCAN_TILE];
    int t = threadIdx.x;
    int i = blockIdx.x * SCAN_TILE + t;
    red[t] = (i < n) ? g_deg[i] : 0;
    __syncthreads();
    for (int off = SCAN_TILE / 2; off > 0; off >>= 1) {
        if (t < off) red[t] += red[t + off];
        __syncthreads();
    }
    if (t == 0) g_tilesum[blockIdx.x] = red[0];
}

__global__ void scanB_kernel() {
    __shared__ int s[128];
    int t = threadIdx.x;
    s[t] = (t < SCAN_NBLK) ? g_tilesum[t] : 0;
    __syncthreads();
    for (int off = 1; off < 128; off <<= 1) {
        int v = (t >= off) ? s[t - off] : 0;
        __syncthreads();
        s[t] += v;
        __syncthreads();
    }
    if (t < SCAN_NBLK) g_tileoff[t] = (t == 0) ? 0 : s[t - 1];
}

__global__ void scanC_kernel(int n, int E) {
    __shared__ int s[SCAN_TILE];
    int t = threadIdx.x;
    int i = blockIdx.x * SCAN_TILE + t;
    int v = (i < n) ? g_deg[i] : 0;
    s[t] = v;
    __syncthreads();
    for (int off = 1; off < SCAN_TILE; off <<= 1) {
        int u = (t >= off) ? s[t - off] : 0;
        __syncthreads();
        s[t] += u;
        __syncthreads();
    }
    if (i < n) {
        int excl = g_tileoff[blockIdx.x] + s[t] - v;
        g_rowstart[i] = excl;
        g_cursor[i]   = excl;
        if (i == n - 1) g_rowstart[n] = E;
    }
}

__global__ void scatter_kernel(const void* __restrict__ src,
                               const void* __restrict__ dst, int E) {
    int is64 = g_is64;
    for (int e = blockIdx.x * blockDim.x + threadIdx.x; e < E; e += gridDim.x * blockDim.x) {
        int d = load_idx(dst, e, is64);
        int pos = atomicAdd(&g_cursor[d], 1);
        g_csr[pos] = load_idx(src, e, is64);
    }
}

// ---------------- bf16-split tensor-core dual GEMM ---------------------------
// C[M x 2*halfN] = A[M x K] @ [W0 | W1] using mma.m16n8k16 bf16, 3-term split:
//   A*B ~= Ah*Bh + Ah*Bl + Al*Bh  (drop Al*Bl ~ 2^-18 relative)
#define TBM 128
#define TBN 128
#define TBK 32
#define APAD 8
#define ASTR (TBM + APAD)
#define WSTR (TBN + APAD)

// pack two floats' bf16-hi parts into one .b32 (low half = first k)
__device__ __forceinline__ uint32_t pack_hi(float f0, float f1,
                                            float& r0, float& r1) {
    __nv_bfloat16 h0 = __float2bfloat16_rn(f0);
    __nv_bfloat16 h1 = __float2bfloat16_rn(f1);
    r0 = f0 - __bfloat162float(h0);
    r1 = f1 - __bfloat162float(h1);
    __nv_bfloat162 p = __halves2bfloat162(h0, h1);
    return *reinterpret_cast<uint32_t*>(&p);
}

__device__ __forceinline__ uint32_t pack_bf2(float f0, float f1) {
    __nv_bfloat162 p = __floats2bfloat162_rn(f0, f1);
    return *reinterpret_cast<uint32_t*>(&p);
}

__device__ __forceinline__ void mma_bf16(float* c, uint32_t a0, uint32_t a1,
                                         uint32_t a2, uint32_t a3,
                                         uint32_t b0, uint32_t b1) {
    asm volatile(
        "mma.sync.aligned.m16n8k16.row.col.f32.bf16.bf16.f32 "
        "{%0,%1,%2,%3}, {%4,%5,%6,%7}, {%8,%9}, {%0,%1,%2,%3};"
        : "+f"(c[0]), "+f"(c[1]), "+f"(c[2]), "+f"(c[3])
        : "r"(a0), "r"(a1), "r"(a2), "r"(a3), "r"(b0), "r"(b1));
}

__global__ __launch_bounds__(256) void gemm_bf16_kernel(
    const float* __restrict__ Aext,
    const float* __restrict__ W0,
    const float* __restrict__ W1,
    int M, int K, int halfN, int layer)
{
    const float* __restrict__ A = (layer == 1) ? Aext : g_h1;
    float* __restrict__ C       = (layer == 1) ? g_t1 : g_t2;

    const int N  = 2 * halfN;
    const int bn = blockIdx.x * TBN;
    const int bm = blockIdx.y * TBM;

    __shared__ float As[TBK][ASTR];   // transposed A tile: As[k][row]
    __shared__ float Ws[TBK][WSTR];   // Ws[k][col]

    const int tid  = threadIdx.x;
    const int lane = tid & 31;
    const int warp = tid >> 5;
    const int wm = warp >> 1;          // 0..3 -> 32-row slab
    const int wn = warp & 1;           // 0..1 -> 64-col slab

    const int arow  = tid >> 1;
    const int akb   = (tid & 1) * 16;
    const int aValid = (bm + arow < M);
    const int bkr   = tid >> 3;
    const int bcb   = (tid & 7) * 16;
    const int gcol0 = bn + bcb;
    const float* __restrict__ Wp = (gcol0 < halfN) ? W0 : W1;
    const int wc = (gcol0 < halfN) ? gcol0 : gcol0 - halfN;

    float acc[2][8][4];
#pragma unroll
    for (int i = 0; i < 2; i++)
#pragma unroll
        for (int j = 0; j < 8; j++)
#pragma unroll
            for (int q = 0; q < 4; q++) acc[i][j][q] = 0.f;

    const int kq = lane & 3;           // fragment k-group (x2 within k16 halves)
    const int fr = lane >> 2;          // fragment row/col within tile

    for (int k0 = 0; k0 < K; k0 += TBK) {
#pragma unroll
        for (int v = 0; v < 4; v++) {
            float4 av = make_float4(0.f, 0.f, 0.f, 0.f);
            if (aValid)
                av = *reinterpret_cast<const float4*>(
                    &A[(size_t)(bm + arow) * K + k0 + akb + v * 4]);
            As[akb + v * 4 + 0][arow] = av.x;
            As[akb + v * 4 + 1][arow] = av.y;
            As[akb + v * 4 + 2][arow] = av.z;
            As[akb + v * 4 + 3][arow] = av.w;
        }
#pragma unroll
        for (int v = 0; v < 4; v++) {
            float4 bv = *reinterpret_cast<const float4*>(
                &Wp[(size_t)(k0 + bkr) * halfN + wc + v * 4]);
            *reinterpret_cast<float4*>(&Ws[bkr][bcb + v * 4]) = bv;
        }
        __syncthreads();

#pragma unroll
        for (int ks = 0; ks < TBK / 16; ks++) {   // 2 k16 slices
            const int kb = ks * 16 + kq * 2;      // this lane's k base (lo 8-half)
            // ---- B fragments for 8 n-tiles (shared across both m-tiles)
            uint32_t bhi[8][2], blo[8][2];
#pragma unroll
            for (int nj = 0; nj < 8; nj++) {
                int c = wn * 64 + nj * 8 + fr;
                float r0, r1, r2, r3;
                bhi[nj][0] = pack_hi(Ws[kb][c],     Ws[kb + 1][c],     r0, r1);
                bhi[nj][1] = pack_hi(Ws[kb + 8][c], Ws[kb + 9][c],     r2, r3);
                blo[nj][0] = pack_bf2(r0, r1);
                blo[nj][1] = pack_bf2(r2, r3);
            }
#pragma unroll
            for (int mi = 0; mi < 2; mi++) {
                int r = wm * 32 + mi * 16 + fr;
                float q0, q1, q2, q3, q4, q5, q6, q7;
                uint32_t ah0 = pack_hi(As[kb][r],     As[kb + 1][r],     q0, q1);
                uint32_t ah1 = pack_hi(As[kb][r + 8], As[kb + 1][r + 8], q2, q3);
                uint32_t ah2 = pack_hi(As[kb + 8][r],     As[kb + 9][r],     q4, q5);
                uint32_t ah3 = pack_hi(As[kb + 8][r + 8], As[kb + 9][r + 8], q6, q7);
                uint32_t al0 = pack_bf2(q0, q1);
                uint32_t al1 = pack_bf2(q2, q3);
                uint32_t al2 = pack_bf2(q4, q5);
                uint32_t al3 = pack_bf2(q6, q7);
#pragma unroll
                for (int nj = 0; nj < 8; nj++) {
                    mma_bf16(acc[mi][nj], ah0, ah1, ah2, ah3, bhi[nj][0], bhi[nj][1]);
                    mma_bf16(acc[mi][nj], ah0, ah1, ah2, ah3, blo[nj][0], blo[nj][1]);
                    mma_bf16(acc[mi][nj], al0, al1, al2, al3, bhi[nj][0], bhi[nj][1]);
                }
            }
        }
        __syncthreads();
    }

#pragma unroll
    for (int mi = 0; mi < 2; mi++) {
        int r0 = bm + wm * 32 + mi * 16 + (lane >> 2);
#pragma unroll
        for (int nj = 0; nj < 8; nj++) {
            int col = bn + wn * 64 + nj * 8 + (lane & 3) * 2;
            if (r0 < M)
                *reinterpret_cast<float2*>(&C[(size_t)r0 * N + col]) =
                    make_float2(acc[mi][nj][0], acc[mi][nj][1]);
            if (r0 + 8 < M)
                *reinterpret_cast<float2*>(&C[(size_t)(r0 + 8) * N + col]) =
                    make_float2(acc[mi][nj][2], acc[mi][nj][3]);
        }
    }
}

// ---------------- aggregation + epilogue (simple loop — unroll regresses) ----
__global__ void agg_epilogue1_kernel(const float* __restrict__ b1, int n) {
    int node = blockIdx.x * blockDim.y + threadIdx.y;
    if (node >= n) return;
    int j = threadIdx.x;   // 0..127
    int beg = g_rowstart[node];
    int end = g_rowstart[node + 1];
    float acc = 0.f;
    for (int e = beg; e < end; e++) {
        int s = g_csr[e];
        acc += g_t1[(size_t)s * 256 + 128 + j];
    }
    float inv = 1.f / fmaxf((float)(end - beg), 1.f);
    float v = g_t1[(size_t)node * 256 + j] + acc * inv + b1[j];
    g_h1[(size_t)node * 128 + j] = fmaxf(v, 0.f);
}

__global__ void agg_epilogue2_kernel(const float* __restrict__ b2,
                                     float* __restrict__ out, int n) {
    int node = blockIdx.x * blockDim.y + threadIdx.y;
    if (node >= n) return;
    int j = threadIdx.x;   // 0..63
    int beg = g_rowstart[node];
    int end = g_rowstart[node + 1];
    float acc = 0.f;
    for (int e = beg; e < end; e++) {
        int s = g_csr[e];
        acc += g_t2[(size_t)s * 128 + 64 + j];
    }
    float inv = 1.f / fmaxf((float)(end - beg), 1.f);
    out[(size_t)node * 64 + j] = g_t2[(size_t)node * 128 + j] + acc * inv + b2[j];
}

// ---------------- launch (sequential, single stream) -------------------------
extern "C" void kernel_launch(void* const* d_in, const int* in_sizes, int n_in,
                              void* d_out, int out_size) {
    const float* feat     = (const float*)d_in[0];
    const void*  src      = d_in[1];
    const void*  dst      = d_in[2];
    const float* W_self1  = (const float*)d_in[3];
    const float* W_neigh1 = (const float*)d_in[4];
    const float* b1       = (const float*)d_in[5];
    const float* W_self2  = (const float*)d_in[6];
    const float* W_neigh2 = (const float*)d_in[7];
    const float* b2       = (const float*)d_in[8];
    float* out = (float*)d_out;

    const int N = in_sizes[0] / D_IN;   // 50000
    const int E = in_sizes[1];          // 800000

    // ---- index dtype detection + CSR build (shared by both layers)
    detect_kernel<<<1, 256>>>((const int*)dst, E);
    zero_deg_kernel<<<(N + 255) / 256, 256>>>(N);
    hist_kernel<<<2048, 256>>>(dst, E);
    scanA_kernel<<<SCAN_NBLK, SCAN_TILE>>>(N);
    scanB_kernel<<<1, 128>>>();
    scanC_kernel<<<SCAN_NBLK, SCAN_TILE>>>(N, E);
    scatter_kernel<<<2048, 256>>>(src, dst, E);

    // ---- layer 1: feat @ [W_self1 | W_neigh1] -> g_t1 [N x 256]
    {
        dim3 grid(256 / TBN, (N + TBM - 1) / TBM);
        gemm_bf16_kernel<<<grid, 256>>>(feat, W_self1, W_neigh1, N, D_IN, D_HID, 1);
    }
    {
        dim3 block(128, 2);
        agg_epilogue1_kernel<<<(N + 1) / 2, block>>>(b1, N);
    }

    // ---- layer 2: g_h1 @ [W_self2 | W_neigh2] -> g_t2 [N x 128]
    {
        dim3 grid(128 / TBN, (N + TBM - 1) / TBM);
        gemm_bf16_kernel<<<grid, 256>>>(feat, W_self2, W_neigh2, N, D_HID, D_OUT, 2);
    }
    {
        dim3 block(64, 4);
        agg_epilogue2_kernel<<<(N + 3) / 4, block>>>(b2, out, N);
    }
}

// round 14
// speedup vs baseline: 2.0141x; 1.1836x over previous
#include <cuda_runtime.h>
#include <cuda_bf16.h>
#include <cstdint>

// Problem constants (SAGEEncoder: N=50000, E=800000, IN=128, HID=128, OUT=64)
#define NMAX 50000
#define EMAX 800000
#define D_IN 128
#define D_HID 128
#define D_OUT 64

#define SCAN_TILE 512
#define SCAN_NBLK ((NMAX + SCAN_TILE - 1) / SCAN_TILE)   // 98

// ---------------- scratch (static device globals; no allocation) -------------
__device__ __align__(16) int   g_deg[NMAX];
__device__ __align__(16) int   g_rowstart[NMAX + 1];
__device__ __align__(16) int   g_cursor[NMAX];
__device__ __align__(16) int   g_csr[EMAX];
__device__ __align__(16) int   g_tilesum[SCAN_NBLK];
__device__ __align__(16) int   g_tileoff[SCAN_NBLK];
__device__ __align__(16) float g_t1[(size_t)NMAX * 256]; // [n][0:128)=feat@Wself1, [128:256)=feat@Wneigh1
__device__ __align__(16) float g_h1[(size_t)NMAX * 128]; // relu'd layer-1 output
__device__ __align__(16) float g_t2[(size_t)NMAX * 128]; // [n][0:64)=h1@Wself2, [64:128)=h1@Wneigh2
__device__ int g_is64;

// ---------------- index dtype detection --------------------------------------
__global__ void detect_kernel(const int* __restrict__ idx32, int E) {
    __shared__ int nz;
    if (threadIdx.x == 0) nz = 0;
    __syncthreads();
    int i = threadIdx.x;
    if (idx32[2 * i + 1] != 0) atomicAdd(&nz, 1);
    __syncthreads();
    if (threadIdx.x == 0) g_is64 = (nz == 0) ? 1 : 0;
}

__device__ __forceinline__ int load_idx(const void* p, int e, int is64) {
    if (is64) return (int)((const long long*)p)[e];
    return ((const int*)p)[e];
}

// ---------------- CSR build --------------------------------------------------
__global__ void zero_deg_kernel(int n) {
    int i = blockIdx.x * blockDim.x + threadIdx.x;
    if (i < n) g_deg[i] = 0;
}

__global__ void hist_kernel(const void* __restrict__ dst, int E) {
    int is64 = g_is64;
    for (int e = blockIdx.x * blockDim.x + threadIdx.x; e < E; e += gridDim.x * blockDim.x)
        atomicAdd(&g_deg[load_idx(dst, e, is64)], 1);
}

__global__ void scanA_kernel(int n) {
    __shared__ int red[SCAN_TILE];
    int t = threadIdx.x;
    int i = blockIdx.x * SCAN_TILE + t;
    red[t] = (i < n) ? g_deg[i] : 0;
    __syncthreads();
    for (int off = SCAN_TILE / 2; off > 0; off >>= 1) {
        if (t < off) red[t] += red[t + off];
        __syncthreads();
    }
    if (t == 0) g_tilesum[blockIdx.x] = red[0];
}

__global__ void scanB_kernel() {
    __shared__ int s[128];
    int t = threadIdx.x;
    s[t] = (t < SCAN_NBLK) ? g_tilesum[t] : 0;
    __syncthreads();
    for (int off = 1; off < 128; off <<= 1) {
        int v = (t >= off) ? s[t - off] : 0;
        __syncthreads();
        s[t] += v;
        __syncthreads();
    }
    if (t < SCAN_NBLK) g_tileoff[t] = (t == 0) ? 0 : s[t - 1];
}

__global__ void scanC_kernel(int n, int E) {
    __shared__ int s[SCAN_TILE];
    int t = threadIdx.x;
    int i = blockIdx.x * SCAN_TILE + t;
    int v = (i < n) ? g_deg[i] : 0;
    s[t] = v;
    __syncthreads();
    for (int off = 1; off < SCAN_TILE; off <<= 1) {
        int u = (t >= off) ? s[t - off] : 0;
        __syncthreads();
        s[t] += u;
        __syncthreads();
    }
    if (i < n) {
        int excl = g_tileoff[blockIdx.x] + s[t] - v;
        g_rowstart[i] = excl;
        g_cursor[i]   = excl;
        if (i == n - 1) g_rowstart[n] = E;
    }
}

__global__ void scatter_kernel(const void* __restrict__ src,
                               const void* __restrict__ dst, int E) {
    int is64 = g_is64;
    for (int e = blockIdx.x * blockDim.x + threadIdx.x; e < E; e += gridDim.x * blockDim.x) {
        int d = load_idx(dst, e, is64);
        int pos = atomicAdd(&g_cursor[d], 1);
        g_csr[pos] = load_idx(src, e, is64);
    }
}

// ---------------- bf16-split tensor-core dual GEMM ---------------------------
// C[M x 2*halfN] = A[M x K] @ [W0 | W1] using mma.m16n8k16 bf16, 3-term split:
//   A*B ~= Ah*Bh + Ah*Bl + Al*Bh  (drop Al*Bl ~ 2^-18 relative)
#define TBM 128
#define TBN 128
#define TBK 32
#define APAD 8
#define ASTR (TBM + APAD)
#define WSTR (TBN + APAD)

__device__ __forceinline__ uint32_t pack_hi(float f0, float f1,
                                            float& r0, float& r1) {
    __nv_bfloat16 h0 = __float2bfloat16_rn(f0);
    __nv_bfloat16 h1 = __float2bfloat16_rn(f1);
    r0 = f0 - __bfloat162float(h0);
    r1 = f1 - __bfloat162float(h1);
    __nv_bfloat162 p = __halves2bfloat162(h0, h1);
    return *reinterpret_cast<uint32_t*>(&p);
}

__device__ __forceinline__ uint32_t pack_bf2(float f0, float f1) {
    __nv_bfloat162 p = __floats2bfloat162_rn(f0, f1);
    return *reinterpret_cast<uint32_t*>(&p);
}

__device__ __forceinline__ void mma_bf16(float* c, uint32_t a0, uint32_t a1,
                                         uint32_t a2, uint32_t a3,
                                         uint32_t b0, uint32_t b1) {
    asm volatile(
        "mma.sync.aligned.m16n8k16.row.col.f32.bf16.bf16.f32 "
        "{%0,%1,%2,%3}, {%4,%5,%6,%7}, {%8,%9}, {%0,%1,%2,%3};"
        : "+f"(c[0]), "+f"(c[1]), "+f"(c[2]), "+f"(c[3])
        : "r"(a0), "r"(a1), "r"(a2), "r"(a3), "r"(b0), "r"(b1));
}

__global__ __launch_bounds__(256) void gemm_bf16_kernel(
    const float* __restrict__ Aext,
    const float* __restrict__ W0,
    const float* __restrict__ W1,
    int M, int K, int halfN, int layer)
{
    const float* __restrict__ A = (layer == 1) ? Aext : g_h1;
    float* __restrict__ C       = (layer == 1) ? g_t1 : g_t2;

    const int N  = 2 * halfN;
    const int bn = blockIdx.x * TBN;
    const int bm = blockIdx.y * TBM;

    __shared__ float As[TBK][ASTR];   // transposed A tile: As[k][row]
    __shared__ float Ws[TBK][WSTR];   // Ws[k][col]

    const int tid  = threadIdx.x;
    const int lane = tid & 31;
    const int warp = tid >> 5;
    const int wm = warp >> 1;
    const int wn = warp & 1;

    const int arow  = tid >> 1;
    const int akb   = (tid & 1) * 16;
    const int aValid = (bm + arow < M);
    const int bkr   = tid >> 3;
    const int bcb   = (tid & 7) * 16;
    const int gcol0 = bn + bcb;
    const float* __restrict__ Wp = (gcol0 < halfN) ? W0 : W1;
    const int wc = (gcol0 < halfN) ? gcol0 : gcol0 - halfN;

    float acc[2][8][4];
#pragma unroll
    for (int i = 0; i < 2; i++)
#pragma unroll
        for (int j = 0; j < 8; j++)
#pragma unroll
            for (int q = 0; q < 4; q++) acc[i][j][q] = 0.f;

    const int kq = lane & 3;
    const int fr = lane >> 2;

    for (int k0 = 0; k0 < K; k0 += TBK) {
#pragma unroll
        for (int v = 0; v < 4; v++) {
            float4 av = make_float4(0.f, 0.f, 0.f, 0.f);
            if (aValid)
                av = *reinterpret_cast<const float4*>(
                    &A[(size_t)(bm + arow) * K + k0 + akb + v * 4]);
            As[akb + v * 4 + 0][arow] = av.x;
            As[akb + v * 4 + 1][arow] = av.y;
            As[akb + v * 4 + 2][arow] = av.z;
            As[akb + v * 4 + 3][arow] = av.w;
        }
#pragma unroll
        for (int v = 0; v < 4; v++) {
            float4 bv = *reinterpret_cast<const float4*>(
                &Wp[(size_t)(k0 + bkr) * halfN + wc + v * 4]);
            *reinterpret_cast<float4*>(&Ws[bkr][bcb + v * 4]) = bv;
        }
        __syncthreads();

#pragma unroll
        for (int ks = 0; ks < TBK / 16; ks++) {
            const int kb = ks * 16 + kq * 2;
            uint32_t bhi[8][2], blo[8][2];
#pragma unroll
            for (int nj = 0; nj < 8; nj++) {
                int c = wn * 64 + nj * 8 + fr;
                float r0, r1, r2, r3;
                bhi[nj][0] = pack_hi(Ws[kb][c],     Ws[kb + 1][c],     r0, r1);
                bhi[nj][1] = pack_hi(Ws[kb + 8][c], Ws[kb + 9][c],     r2, r3);
                blo[nj][0] = pack_bf2(r0, r1);
                blo[nj][1] = pack_bf2(r2, r3);
            }
#pragma unroll
            for (int mi = 0; mi < 2; mi++) {
                int r = wm * 32 + mi * 16 + fr;
                float q0, q1, q2, q3, q4, q5, q6, q7;
                uint32_t ah0 = pack_hi(As[kb][r],     As[kb + 1][r],     q0, q1);
                uint32_t ah1 = pack_hi(As[kb][r + 8], As[kb + 1][r + 8], q2, q3);
                uint32_t ah2 = pack_hi(As[kb + 8][r],     As[kb + 9][r],     q4, q5);
                uint32_t ah3 = pack_hi(As[kb + 8][r + 8], As[kb + 9][r + 8], q6, q7);
                uint32_t al0 = pack_bf2(q0, q1);
                uint32_t al1 = pack_bf2(q2, q3);
                uint32_t al2 = pack_bf2(q4, q5);
                uint32_t al3 = pack_bf2(q6, q7);
#pragma unroll
                for (int nj = 0; nj < 8; nj++) {
                    mma_bf16(acc[mi][nj], ah0, ah1, ah2, ah3, bhi[nj][0], bhi[nj][1]);
                    mma_bf16(acc[mi][nj], ah0, ah1, ah2, ah3, blo[nj][0], blo[nj][1]);
                    mma_bf16(acc[mi][nj], al0, al1, al2, al3, bhi[nj][0], bhi[nj][1]);
                }
            }
        }
        __syncthreads();
    }

#pragma unroll
    for (int mi = 0; mi < 2; mi++) {
        int r0 = bm + wm * 32 + mi * 16 + (lane >> 2);
#pragma unroll
        for (int nj = 0; nj < 8; nj++) {
            int col = bn + wn * 64 + nj * 8 + (lane & 3) * 2;
            if (r0 < M)
                *reinterpret_cast<float2*>(&C[(size_t)r0 * N + col]) =
                    make_float2(acc[mi][nj][0], acc[mi][nj][1]);
            if (r0 + 8 < M)
                *reinterpret_cast<float2*>(&C[(size_t)(r0 + 8) * N + col]) =
                    make_float2(acc[mi][nj][2], acc[mi][nj][3]);
        }
    }
}

// ---------------- aggregation + epilogue (warp-per-node, vector loads) -------
// layer 1: warp handles one node; lane -> float4 at column 4*lane (128 cols).
// One LDG.128 per warp per edge covers the whole 512B row; serial loop keeps
// MLP_p1 low (front-batched gathers regress via L1tex-queue contention).
__global__ __launch_bounds__(256) void agg_epilogue1_kernel(
    const float* __restrict__ b1, int n)
{
    int warp = threadIdx.x >> 5;
    int lane = threadIdx.x & 31;
    int node = blockIdx.x * 8 + warp;
    if (node >= n) return;
    int beg = g_rowstart[node];
    int end = g_rowstart[node + 1];
    float4 acc = make_float4(0.f, 0.f, 0.f, 0.f);
    for (int e = beg; e < end; e++) {
        int s = g_csr[e];                       // warp-broadcast load
        float4 v = *reinterpret_cast<const float4*>(
            &g_t1[(size_t)s * 256 + 128 + lane * 4]);
        acc.x += v.x; acc.y += v.y; acc.z += v.z; acc.w += v.w;
    }
    float inv = 1.f / fmaxf((float)(end - beg), 1.f);
    float4 self = *reinterpret_cast<const float4*>(&g_t1[(size_t)node * 256 + lane * 4]);
    float4 bb   = *reinterpret_cast<const float4*>(&b1[lane * 4]);
    float4 r;
    r.x = fmaxf(self.x + acc.x * inv + bb.x, 0.f);
    r.y = fmaxf(self.y + acc.y * inv + bb.y, 0.f);
    r.z = fmaxf(self.z + acc.z * inv + bb.z, 0.f);
    r.w = fmaxf(self.w + acc.w * inv + bb.w, 0.f);
    *reinterpret_cast<float4*>(&g_h1[(size_t)node * 128 + lane * 4]) = r;
}

// layer 2: warp per node; lane -> float2 at column 2*lane (64 cols).
__global__ __launch_bounds__(256) void agg_epilogue2_kernel(
    const float* __restrict__ b2, float* __restrict__ out, int n)
{
    int warp = threadIdx.x >> 5;
    int lane = threadIdx.x & 31;
    int node = blockIdx.x * 8 + warp;
    if (node >= n) return;
    int beg = g_rowstart[node];
    int end = g_rowstart[node + 1];
    float2 acc = make_float2(0.f, 0.f);
    for (int e = beg; e < end; e++) {
        int s = g_csr[e];
        float2 v = *reinterpret_cast<const float2*>(
            &g_t2[(size_t)s * 128 + 64 + lane * 2]);
        acc.x += v.x; acc.y += v.y;
    }
    float inv = 1.f / fmaxf((float)(end - beg), 1.f);
    float2 self = *reinterpret_cast<const float2*>(&g_t2[(size_t)node * 128 + lane * 2]);
    float2 bb   = *reinterpret_cast<const float2*>(&b2[lane * 2]);
    float2 r;
    r.x = self.x + acc.x * inv + bb.x;
    r.y = self.y + acc.y * inv + bb.y;
    *reinterpret_cast<float2*>(&out[(size_t)node * 64 + lane * 2]) = r;
}

// ---------------- launch (sequential, single stream) -------------------------
extern "C" void kernel_launch(void* const* d_in, const int* in_sizes, int n_in,
                              void* d_out, int out_size) {
    const float* feat     = (const float*)d_in[0];
    const void*  src      = d_in[1];
    const void*  dst      = d_in[2];
    const float* W_self1  = (const float*)d_in[3];
    const float* W_neigh1 = (const float*)d_in[4];
    const float* b1       = (const float*)d_in[5];
    const float* W_self2  = (const float*)d_in[6];
    const float* W_neigh2 = (const float*)d_in[7];
    const float* b2       = (const float*)d_in[8];
    float* out = (float*)d_out;

    const int N = in_sizes[0] / D_IN;   // 50000
    const int E = in_sizes[1];          // 800000

    // ---- index dtype detection + CSR build (shared by both layers)
    detect_kernel<<<1, 256>>>((const int*)dst, E);
    zero_deg_kernel<<<(N + 255) / 256, 256>>>(N);
    hist_kernel<<<2048, 256>>>(dst, E);
    scanA_kernel<<<SCAN_NBLK, SCAN_TILE>>>(N);
    scanB_kernel<<<1, 128>>>();
    scanC_kernel<<<SCAN_NBLK, SCAN_TILE>>>(N, E);
    scatter_kernel<<<2048, 256>>>(src, dst, E);

    // ---- layer 1: feat @ [W_self1 | W_neigh1] -> g_t1 [N x 256]
    {
        dim3 grid(256 / TBN, (N + TBM - 1) / TBM);
        gemm_bf16_kernel<<<grid, 256>>>(feat, W_self1, W_neigh1, N, D_IN, D_HID, 1);
    }
    agg_epilogue1_kernel<<<(N + 7) / 8, 256>>>(b1, N);

    // ---- layer 2: g_h1 @ [W_self2 | W_neigh2] -> g_t2 [N x 128]
    {
        dim3 grid(128 / TBN, (N + TBM - 1) / TBM);
        gemm_bf16_kernel<<<grid, 256>>>(feat, W_self2, W_neigh2, N, D_HID, D_OUT, 2);
    }
    agg_epilogue2_kernel<<<(N + 7) / 8, 256>>>(b2, out, N);
}

// round 16
// speedup vs baseline: 2.2283x; 1.1064x over previous
#include <cuda_runtime.h>
#include <cuda_bf16.h>
#include <cuda_fp16.h>
#include <cstdint>

// Problem constants (SAGEEncoder: N=50000, E=800000, IN=128, HID=128, OUT=64)
#define NMAX 50000
#define EMAX 800000
#define D_IN 128
#define D_HID 128
#define D_OUT 64

#define SCAN_TILE 512
#define SCAN_NBLK ((NMAX + SCAN_TILE - 1) / SCAN_TILE)   // 98

// ---------------- scratch (static device globals; no allocation) -------------
__device__ __align__(16) int    g_deg[NMAX];
__device__ __align__(16) int    g_rowstart[NMAX + 1];
__device__ __align__(16) int    g_cursor[NMAX];
__device__ __align__(16) int    g_csr[EMAX];
__device__ __align__(16) int    g_tilesum[SCAN_NBLK];
__device__ __align__(16) int    g_tileoff[SCAN_NBLK];
__device__ __align__(16) float  g_t1s[(size_t)NMAX * 128];  // feat@Wself1 (fp32)
__device__ __align__(16) __half g_t1n[(size_t)NMAX * 128];  // feat@Wneigh1 (fp16)
__device__ __align__(16) float  g_h1[(size_t)NMAX * 128];   // relu'd layer-1 output
__device__ __align__(16) float  g_t2s[(size_t)NMAX * 64];   // h1@Wself2 (fp32)
__device__ __align__(16) __half g_t2n[(size_t)NMAX * 64];   // h1@Wneigh2 (fp16)
__device__ int g_is64;

// ---------------- index dtype detection --------------------------------------
__global__ void detect_kernel(const int* __restrict__ idx32, int E) {
    __shared__ int nz;
    if (threadIdx.x == 0) nz = 0;
    __syncthreads();
    int i = threadIdx.x;
    if (idx32[2 * i + 1] != 0) atomicAdd(&nz, 1);
    __syncthreads();
    if (threadIdx.x == 0) g_is64 = (nz == 0) ? 1 : 0;
}

__device__ __forceinline__ int load_idx(const void* p, int e, int is64) {
    if (is64) return (int)((const long long*)p)[e];
    return ((const int*)p)[e];
}

// ---------------- CSR build --------------------------------------------------
__global__ void zero_deg_kernel(int n) {
    int i = blockIdx.x * blockDim.x + threadIdx.x;
    if (i < n) g_deg[i] = 0;
}

__global__ void hist_kernel(const void* __restrict__ dst, int E) {
    int is64 = g_is64;
    for (int e = blockIdx.x * blockDim.x + threadIdx.x; e < E; e += gridDim.x * blockDim.x)
        atomicAdd(&g_deg[load_idx(dst, e, is64)], 1);
}

__global__ void scanA_kernel(int n) {
    __shared__ int red[SCAN_TILE];
    int t = threadIdx.x;
    int i = blockIdx.x * SCAN_TILE + t;
    red[t] = (i < n) ? g_deg[i] : 0;
    __syncthreads();
    for (int off = SCAN_TILE / 2; off > 0; off >>= 1) {
        if (t < off) red[t] += red[t + off];
        __syncthreads();
    }
    if (t == 0) g_tilesum[blockIdx.x] = red[0];
}

__global__ void scanB_kernel() {
    __shared__ int s[128];
    int t = threadIdx.x;
    s[t] = (t < SCAN_NBLK) ? g_tilesum[t] : 0;
    __syncthreads();
    for (int off = 1; off < 128; off <<= 1) {
        int v = (t >= off) ? s[t - off] : 0;
        __syncthreads();
        s[t] += v;
        __syncthreads();
    }
    if (t < SCAN_NBLK) g_tileoff[t] = (t == 0) ? 0 : s[t - 1];
}

__global__ void scanC_kernel(int n, int E) {
    __shared__ int s[SCAN_TILE];
    int t = threadIdx.x;
    int i = blockIdx.x * SCAN_TILE + t;
    int v = (i < n) ? g_deg[i] : 0;
    s[t] = v;
    __syncthreads();
    for (int off = 1; off < SCAN_TILE; off <<= 1) {
        int u = (t >= off) ? s[t - off] : 0;
        __syncthreads();
        s[t] += u;
        __syncthreads();
    }
    if (i < n) {
        int excl = g_tileoff[blockIdx.x] + s[t] - v;
        g_rowstart[i] = excl;
        g_cursor[i]   = excl;
        if (i == n - 1) g_rowstart[n] = E;
    }
}

__global__ void scatter_kernel(const void* __restrict__ src,
                               const void* __restrict__ dst, int E) {
    int is64 = g_is64;
    for (int e = blockIdx.x * blockDim.x + threadIdx.x; e < E; e += gridDim.x * blockDim.x) {
        int d = load_idx(dst, e, is64);
        int pos = atomicAdd(&g_cursor[d], 1);
        g_csr[pos] = load_idx(src, e, is64);
    }
}

// ---------------- bf16-split tensor-core dual GEMM ---------------------------
// D[M x 2*halfN] = A[M x K] @ [W0 | W1] via mma.m16n8k16 bf16 3-term split.
// Epilogue: self half (cols < halfN) -> fp32 buffer; neigh half -> fp16 buffer.
#define TBM 128
#define TBN 128
#define TBK 32
#define APAD 8
#define ASTR (TBM + APAD)
#define WSTR (TBN + APAD)

__device__ __forceinline__ uint32_t pack_hi(float f0, float f1,
                                            float& r0, float& r1) {
    __nv_bfloat16 h0 = __float2bfloat16_rn(f0);
    __nv_bfloat16 h1 = __float2bfloat16_rn(f1);
    r0 = f0 - __bfloat162float(h0);
    r1 = f1 - __bfloat162float(h1);
    __nv_bfloat162 p = __halves2bfloat162(h0, h1);
    return *reinterpret_cast<uint32_t*>(&p);
}

__device__ __forceinline__ uint32_t pack_bf2(float f0, float f1) {
    __nv_bfloat162 p = __floats2bfloat162_rn(f0, f1);
    return *reinterpret_cast<uint32_t*>(&p);
}

__device__ __forceinline__ void mma_bf16(float* c, uint32_t a0, uint32_t a1,
                                         uint32_t a2, uint32_t a3,
                                         uint32_t b0, uint32_t b1) {
    asm volatile(
        "mma.sync.aligned.m16n8k16.row.col.f32.bf16.bf16.f32 "
        "{%0,%1,%2,%3}, {%4,%5,%6,%7}, {%8,%9}, {%0,%1,%2,%3};"
        : "+f"(c[0]), "+f"(c[1]), "+f"(c[2]), "+f"(c[3])
        : "r"(a0), "r"(a1), "r"(a2), "r"(a3), "r"(b0), "r"(b1));
}

__device__ __forceinline__ void store_pair(int layer, int halfN, int row,
                                           int col, float v0, float v1) {
    if (layer == 1) {
        if (col < halfN)
            *reinterpret_cast<float2*>(&g_t1s[(size_t)row * 128 + col]) =
                make_float2(v0, v1);
        else
            *reinterpret_cast<__half2*>(&g_t1n[(size_t)row * 128 + (col - halfN)]) =
                __floats2half2_rn(v0, v1);
    } else {
        if (col < halfN)
            *reinterpret_cast<float2*>(&g_t2s[(size_t)row * 64 + col]) =
                make_float2(v0, v1);
        else
            *reinterpret_cast<__half2*>(&g_t2n[(size_t)row * 64 + (col - halfN)]) =
                __floats2half2_rn(v0, v1);
    }
}

__global__ __launch_bounds__(256) void gemm_bf16_kernel(
    const float* __restrict__ Aext,
    const float* __restrict__ W0,
    const float* __restrict__ W1,
    int M, int K, int halfN, int layer)
{
    const float* __restrict__ A = (layer == 1) ? Aext : g_h1;

    const int bn = blockIdx.x * TBN;
    const int bm = blockIdx.y * TBM;

    __shared__ float As[TBK][ASTR];   // transposed A tile: As[k][row]
    __shared__ float Ws[TBK][WSTR];   // Ws[k][col]

    const int tid  = threadIdx.x;
    const int lane = tid & 31;
    const int warp = tid >> 5;
    const int wm = warp >> 1;
    const int wn = warp & 1;

    const int arow  = tid >> 1;
    const int akb   = (tid & 1) * 16;
    const int aValid = (bm + arow < M);
    const int bkr   = tid >> 3;
    const int bcb   = (tid & 7) * 16;
    const int gcol0 = bn + bcb;
    const float* __restrict__ Wp = (gcol0 < halfN) ? W0 : W1;
    const int wc = (gcol0 < halfN) ? gcol0 : gcol0 - halfN;

    float acc[2][8][4];
#pragma unroll
    for (int i = 0; i < 2; i++)
#pragma unroll
        for (int j = 0; j < 8; j++)
#pragma unroll
            for (int q = 0; q < 4; q++) acc[i][j][q] = 0.f;

    const int kq = lane & 3;
    const int fr = lane >> 2;

    for (int k0 = 0; k0 < K; k0 += TBK) {
#pragma unroll
        for (int v = 0; v < 4; v++) {
            float4 av = make_float4(0.f, 0.f, 0.f, 0.f);
            if (aValid)
                av = *reinterpret_cast<const float4*>(
                    &A[(size_t)(bm + arow) * K + k0 + akb + v * 4]);
            As[akb + v * 4 + 0][arow] = av.x;
            As[akb + v * 4 + 1][arow] = av.y;
            As[akb + v * 4 + 2][arow] = av.z;
            As[akb + v * 4 + 3][arow] = av.w;
        }
#pragma unroll
        for (int v = 0; v < 4; v++) {
            float4 bv = *reinterpret_cast<const float4*>(
                &Wp[(size_t)(k0 + bkr) * halfN + wc + v * 4]);
            *reinterpret_cast<float4*>(&Ws[bkr][bcb + v * 4]) = bv;
        }
        __syncthreads();

#pragma unroll
        for (int ks = 0; ks < TBK / 16; ks++) {
            const int kb = ks * 16 + kq * 2;
            uint32_t bhi[8][2], blo[8][2];
#pragma unroll
            for (int nj = 0; nj < 8; nj++) {
                int c = wn * 64 + nj * 8 + fr;
                float r0, r1, r2, r3;
                bhi[nj][0] = pack_hi(Ws[kb][c],     Ws[kb + 1][c],     r0, r1);
                bhi[nj][1] = pack_hi(Ws[kb + 8][c], Ws[kb + 9][c],     r2, r3);
                blo[nj][0] = pack_bf2(r0, r1);
                blo[nj][1] = pack_bf2(r2, r3);
            }
#pragma unroll
            for (int mi = 0; mi < 2; mi++) {
                int r = wm * 32 + mi * 16 + fr;
                float q0, q1, q2, q3, q4, q5, q6, q7;
                uint32_t ah0 = pack_hi(As[kb][r],     As[kb + 1][r],     q0, q1);
                uint32_t ah1 = pack_hi(As[kb][r + 8], As[kb + 1][r + 8], q2, q3);
                uint32_t ah2 = pack_hi(As[kb + 8][r],     As[kb + 9][r],     q4, q5);
                uint32_t ah3 = pack_hi(As[kb + 8][r + 8], As[kb + 9][r + 8], q6, q7);
                uint32_t al0 = pack_bf2(q0, q1);
                uint32_t al1 = pack_bf2(q2, q3);
                uint32_t al2 = pack_bf2(q4, q5);
                uint32_t al3 = pack_bf2(q6, q7);
#pragma unroll
                for (int nj = 0; nj < 8; nj++) {
                    mma_bf16(acc[mi][nj], ah0, ah1, ah2, ah3, bhi[nj][0], bhi[nj][1]);
                    mma_bf16(acc[mi][nj], ah0, ah1, ah2, ah3, blo[nj][0], blo[nj][1]);
                    mma_bf16(acc[mi][nj], al0, al1, al2, al3, bhi[nj][0], bhi[nj][1]);
                }
            }
        }
        __syncthreads();
    }

#pragma unroll
    for (int mi = 0; mi < 2; mi++) {
        int r0 = bm + wm * 32 + mi * 16 + (lane >> 2);
#pragma unroll
        for (int nj = 0; nj < 8; nj++) {
            int col = bn + wn * 64 + nj * 8 + (lane & 3) * 2;
            if (r0 < M)
                store_pair(layer, halfN, r0, col, acc[mi][nj][0], acc[mi][nj][1]);
            if (r0 + 8 < M)
                store_pair(layer, halfN, r0 + 8, col, acc[mi][nj][2], acc[mi][nj][3]);
        }
    }
}

// ---------------- aggregation + epilogue (warp-per-node, fp16 gather) --------
// layer 1: warp per node; lane covers cols lane*4..lane*4+3.
// Neigh row = 128 fp16 = 256B per warp (one coalesced 8B load per lane).
__global__ __launch_bounds__(256) void agg_epilogue1_kernel(
    const float* __restrict__ b1, int n)
{
    int warp = threadIdx.x >> 5;
    int lane = threadIdx.x & 31;
    int node = blockIdx.x * 8 + warp;
    if (node >= n) return;
    int beg = g_rowstart[node];
    int end = g_rowstart[node + 1];
    float4 acc = make_float4(0.f, 0.f, 0.f, 0.f);
    for (int e = beg; e < end; e++) {
        int s = g_csr[e];                       // warp-broadcast load
        uint2 hv = *reinterpret_cast<const uint2*>(
            &g_t1n[(size_t)s * 128 + lane * 4]);
        float2 f0 = __half22float2(*reinterpret_cast<__half2*>(&hv.x));
        float2 f1 = __half22float2(*reinterpret_cast<__half2*>(&hv.y));
        acc.x += f0.x; acc.y += f0.y; acc.z += f1.x; acc.w += f1.y;
    }
    float inv = 1.f / fmaxf((float)(end - beg), 1.f);
    float4 self = *reinterpret_cast<const float4*>(&g_t1s[(size_t)node * 128 + lane * 4]);
    float4 bb   = *reinterpret_cast<const float4*>(&b1[lane * 4]);
    float4 r;
    r.x = fmaxf(self.x + acc.x * inv + bb.x, 0.f);
    r.y = fmaxf(self.y + acc.y * inv + bb.y, 0.f);
    r.z = fmaxf(self.z + acc.z * inv + bb.z, 0.f);
    r.w = fmaxf(self.w + acc.w * inv + bb.w, 0.f);
    *reinterpret_cast<float4*>(&g_h1[(size_t)node * 128 + lane * 4]) = r;
}

// layer 2: warp per node; lane covers cols lane*2, lane*2+1 (64 cols).
__global__ __launch_bounds__(256) void agg_epilogue2_kernel(
    const float* __restrict__ b2, float* __restrict__ out, int n)
{
    int warp = threadIdx.x >> 5;
    int lane = threadIdx.x & 31;
    int node = blockIdx.x * 8 + warp;
    if (node >= n) return;
    int beg = g_rowstart[node];
    int end = g_rowstart[node + 1];
    float2 acc = make_float2(0.f, 0.f);
    for (int e = beg; e < end; e++) {
        int s = g_csr[e];
        __half2 hv = *reinterpret_cast<const __half2*>(
            &g_t2n[(size_t)s * 64 + lane * 2]);
        float2 f = __half22float2(hv);
        acc.x += f.x; acc.y += f.y;
    }
    float inv = 1.f / fmaxf((float)(end - beg), 1.f);
    float2 self = *reinterpret_cast<const float2*>(&g_t2s[(size_t)node * 64 + lane * 2]);
    float2 bb   = *reinterpret_cast<const float2*>(&b2[lane * 2]);
    float2 r;
    r.x = self.x + acc.x * inv + bb.x;
    r.y = self.y + acc.y * inv + bb.y;
    *reinterpret_cast<float2*>(&out[(size_t)node * 64 + lane * 2]) = r;
}

// ---------------- launch: CSR build forked parallel to GEMM1 -----------------
extern "C" void kernel_launch(void* const* d_in, const int* in_sizes, int n_in,
                              void* d_out, int out_size) {
    const float* feat     = (const float*)d_in[0];
    const void*  src      = d_in[1];
    const void*  dst      = d_in[2];
    const float* W_self1  = (const float*)d_in[3];
    const float* W_neigh1 = (const float*)d_in[4];
    const float* b1       = (const float*)d_in[5];
    const float* W_self2  = (const float*)d_in[6];
    const float* W_neigh2 = (const float*)d_in[7];
    const float* b2       = (const float*)d_in[8];
    float* out = (float*)d_out;

    const int N = in_sizes[0] / D_IN;   // 50000
    const int E = in_sizes[1];          // 800000

    cudaStream_t s_csr;
    cudaEvent_t evFork, evJoin;
    cudaStreamCreateWithFlags(&s_csr, cudaStreamNonBlocking);
    cudaEventCreateWithFlags(&evFork, cudaEventDisableTiming);
    cudaEventCreateWithFlags(&evJoin, cudaEventDisableTiming);

    cudaEventRecord(evFork, 0);
    cudaStreamWaitEvent(s_csr, evFork, 0);

    // ---- CSR branch (side stream)
    detect_kernel<<<1, 256, 0, s_csr>>>((const int*)dst, E);
    zero_deg_kernel<<<(N + 255) / 256, 256, 0, s_csr>>>(N);
    hist_kernel<<<2048, 256, 0, s_csr>>>(dst, E);
    scanA_kernel<<<SCAN_NBLK, SCAN_TILE, 0, s_csr>>>(N);
    scanB_kernel<<<1, 128, 0, s_csr>>>();
    scanC_kernel<<<SCAN_NBLK, SCAN_TILE, 0, s_csr>>>(N, E);
    scatter_kernel<<<2048, 256, 0, s_csr>>>(src, dst, E);
    cudaEventRecord(evJoin, s_csr);

    // ---- GEMM1 branch (main stream): feat @ [W_self1 | W_neigh1]
    {
        dim3 grid(256 / TBN, (N + TBM - 1) / TBM);
        gemm_bf16_kernel<<<grid, 256>>>(feat, W_self1, W_neigh1, N, D_IN, D_HID, 1);
    }

    // ---- join: agg1 needs CSR + t1
    cudaStreamWaitEvent(0, evJoin, 0);
    agg_epilogue1_kernel<<<(N + 7) / 8, 256>>>(b1, N);

    // ---- layer 2
    {
        dim3 grid(128 / TBN, (N + TBM - 1) / TBM);
        gemm_bf16_kernel<<<grid, 256>>>(feat, W_self2, W_neigh2, N, D_HID, D_OUT, 2);
    }
    agg_epilogue2_kernel<<<(N + 7) / 8, 256>>>(b2, out, N);

    cudaEventDestroy(evFork);
    cudaEventDestroy(evJoin);
    cudaStreamDestroy(s_csr);
}